// round 13
// baseline (speedup 1.0000x reference)
#include <cuda_runtime.h>
#include <cuda_bf16.h>
#include <math.h>
#include <stdint.h>

#define NN   200000
#define EE   600000
#define HH   128
#define OUTD 256
#define BMAXG 1024
#define BM   128
#define SCAN_B 512
#define NSEG 16

// tf32 GEMM tile params
#define ASTRIDE 68     // 64-col chunk + 4 pad
#define WSTRIDE 136    // 128-col + 8 pad

// ---------------- scratch (device globals; no allocation) ----------------
__device__ __nv_bfloat16 g_h1  [(size_t)NN * HH];   // layer-1 output (51.2 MB)
__device__ __nv_bfloat16 g_agg16[(size_t)NN * HH];  // aggregation buffer (51.2 MB)
__device__ int   g_deg [NN];
__device__ int   g_cur [NN];
__device__ int   g_rowptr[NN + 1];
__device__ int   g_scanTmp[NN];
__device__ int   g_bsum[2048];
__device__ int   g_adj [2 * EE];
__device__ int   g_adjT[2 * EE];
__device__ float g_invn[NN];
__device__ float g_gsum[BMAXG * HH];
__device__ int   g_cnt [BMAXG];

// ---------------- helpers ----------------
__device__ __forceinline__ void redAdd4(float* p, float4 v) {
    asm volatile("red.global.add.v4.f32 [%0], {%1,%2,%3,%4};"
                 :: "l"(p), "f"(v.x), "f"(v.y), "f"(v.z), "f"(v.w) : "memory");
}
__device__ __forceinline__ void redAdd2(float* p, float x, float y) {
    asm volatile("red.global.add.v2.f32 [%0], {%1,%2};"
                 :: "l"(p), "f"(x), "f"(y) : "memory");
}
__device__ __forceinline__ float gelu_exact(float v) {
    return 0.5f * v * (1.0f + erff(v * 0.70710678118654752f));
}
__device__ __forceinline__ float4 f4add(float4 a, float4 b) {
    return make_float4(a.x + b.x, a.y + b.y, a.z + b.z, a.w + b.w);
}
__device__ __forceinline__ float tf32r(float x) {
    float y;
    asm("cvt.rna.tf32.f32 %0, %1;" : "=f"(y) : "f"(x));
    return y;
}
__device__ __forceinline__ float4 bf4tof4(uint2 r) {
    float4 f;
    f.x = __uint_as_float(r.x << 16);
    f.y = __uint_as_float(r.x & 0xFFFF0000u);
    f.z = __uint_as_float(r.y << 16);
    f.w = __uint_as_float(r.y & 0xFFFF0000u);
    return f;
}
__device__ __forceinline__ uint2 f4tobf4(float4 s) {
    __nv_bfloat162 h0 = __float22bfloat162_rn(make_float2(s.x, s.y));
    __nv_bfloat162 h1 = __float22bfloat162_rn(make_float2(s.z, s.w));
    uint2 o;
    o.x = *(uint32_t*)&h0;
    o.y = *(uint32_t*)&h1;
    return o;
}
__device__ __forceinline__ void mma_tf32(float* c, const uint32_t* a, uint32_t b0, uint32_t b1) {
    asm volatile(
        "mma.sync.aligned.m16n8k8.row.col.f32.tf32.tf32.f32 "
        "{%0,%1,%2,%3}, {%4,%5,%6,%7}, {%8,%9}, {%0,%1,%2,%3};"
        : "+f"(c[0]), "+f"(c[1]), "+f"(c[2]), "+f"(c[3])
        : "r"(a[0]), "r"(a[1]), "r"(a[2]), "r"(a[3]), "r"(b0), "r"(b1));
}

// ---------------- fused init ----------------
__global__ void init_k(int* __restrict__ deg, int* __restrict__ cur,
                       int* __restrict__ cnt, float* __restrict__ gsum,
                       int n, int b) {
    int i = blockIdx.x * blockDim.x + threadIdx.x;
    int s = gridDim.x * blockDim.x;
    for (int f = i; f < n; f += s) { deg[f] = 0; cur[f] = 0; }
    int g = b * HH;
    for (int f = i; f < g; f += s) gsum[f] = 0.f;
    for (int f = i; f < b; f += s) cnt[f] = 0;
}

// ---------------- degree ----------------
__global__ void deg_k(const int* __restrict__ src, const int* __restrict__ dst,
                      int* __restrict__ deg, int E) {
    int e = blockIdx.x * blockDim.x + threadIdx.x;
    if (e < E) {
        atomicAdd(&deg[src[e]], 1);
        atomicAdd(&deg[dst[e]], 1);
    }
}

// ---------------- exclusive scan (3-kernel) ----------------
__global__ void scan1_k(const int* __restrict__ deg, int* __restrict__ tmp,
                        int* __restrict__ bsum, int n) {
    __shared__ int s[SCAN_B];
    int i = blockIdx.x * SCAN_B + threadIdx.x;
    int v = (i < n) ? deg[i] : 0;
    s[threadIdx.x] = v;
    __syncthreads();
    for (int o = 1; o < SCAN_B; o <<= 1) {
        int t = 0;
        if ((int)threadIdx.x >= o) t = s[threadIdx.x - o];
        __syncthreads();
        if ((int)threadIdx.x >= o) s[threadIdx.x] += t;
        __syncthreads();
    }
    if (i < n) tmp[i] = s[threadIdx.x];
    if (threadIdx.x == SCAN_B - 1) bsum[blockIdx.x] = s[SCAN_B - 1];
}
__global__ void scan2_k(int* __restrict__ bsum, int nb) {
    __shared__ int s[1024];
    int v = ((int)threadIdx.x < nb) ? bsum[threadIdx.x] : 0;
    s[threadIdx.x] = v;
    __syncthreads();
    for (int o = 1; o < 1024; o <<= 1) {
        int t = 0;
        if ((int)threadIdx.x >= o) t = s[threadIdx.x - o];
        __syncthreads();
        if ((int)threadIdx.x >= o) s[threadIdx.x] += t;
        __syncthreads();
    }
    if ((int)threadIdx.x < nb) bsum[threadIdx.x] = s[threadIdx.x];
}
__global__ void scan3_k(const int* __restrict__ deg, const int* __restrict__ tmp,
                        const int* __restrict__ bsum, const int* __restrict__ batch,
                        int* __restrict__ rowptr, float* __restrict__ invn,
                        int* __restrict__ cnt, int n, int Edir) {
    int i = blockIdx.x * SCAN_B + threadIdx.x;
    if (i < n) {
        int boff = (blockIdx.x > 0) ? bsum[blockIdx.x - 1] : 0;
        int d = deg[i];
        rowptr[i] = tmp[i] - d + boff;
        invn[i] = rsqrtf(fmaxf((float)d, 1.0f));
        atomicAdd(&cnt[batch[i]], 1);
    }
    if (i == 0) rowptr[n] = Edir;
}

// ---------------- CSR fill ----------------
__global__ void fill_k(const int* __restrict__ src, const int* __restrict__ dst,
                       const int* __restrict__ x, const int* __restrict__ rowptr,
                       int* __restrict__ cur, int* __restrict__ adj,
                       int* __restrict__ adjT, int E) {
    int e = blockIdx.x * blockDim.x + threadIdx.x;
    if (e < E) {
        int s = src[e], d = dst[e];
        int xs = __ldg(x + s), xd = __ldg(x + d);
        int p = atomicAdd(&cur[d], 1);
        int pd = rowptr[d] + p;
        adj[pd]  = s;
        adjT[pd] = xs;
        int q = atomicAdd(&cur[s], 1);
        int ps = rowptr[s] + q;
        adj[ps]  = d;
        adjT[ps] = xd;
    }
}

// ---------------- layer-1 aggregation: adjT -> hot 153KB emb table; bf16 store ----------------
__global__ void aggregate1_k(const float* __restrict__ emb, const int* __restrict__ rowptr,
                             const int* __restrict__ adjT, const float* __restrict__ invn,
                             __nv_bfloat16* __restrict__ agg16, int n) {
    int lane = threadIdx.x & 31;
    int v = (blockIdx.x * blockDim.x + threadIdx.x) >> 5;
    if (v >= n) return;
    int beg = rowptr[v], end = rowptr[v + 1];
    float4 a0 = make_float4(0.f, 0.f, 0.f, 0.f);
    float4 a1 = a0, a2 = a0, a3 = a0;
    int i = beg;
    for (; i + 4 <= end; i += 4) {
        int t0 = __ldg(adjT + i);
        int t1 = __ldg(adjT + i + 1);
        int t2 = __ldg(adjT + i + 2);
        int t3 = __ldg(adjT + i + 3);
        a0 = f4add(a0, __ldg(((const float4*)(emb + (size_t)t0 * HH)) + lane));
        a1 = f4add(a1, __ldg(((const float4*)(emb + (size_t)t1 * HH)) + lane));
        a2 = f4add(a2, __ldg(((const float4*)(emb + (size_t)t2 * HH)) + lane));
        a3 = f4add(a3, __ldg(((const float4*)(emb + (size_t)t3 * HH)) + lane));
    }
    for (; i < end; i++) {
        int t = __ldg(adjT + i);
        a0 = f4add(a0, __ldg(((const float4*)(emb + (size_t)t * HH)) + lane));
    }
    float4 s = f4add(f4add(a0, a1), f4add(a2, a3));
    float sc = invn[v];
    s.x *= sc; s.y *= sc; s.z *= sc; s.w *= sc;
    ((uint2*)(agg16 + (size_t)v * HH))[lane] = f4tobf4(s);
}

// ---------------- layer-2 aggregation: flat 8-wide bf16 gather; bf16 store ----------------
__global__ void aggregate_k(const __nv_bfloat16* __restrict__ h16, const int* __restrict__ rowptr,
                            const int* __restrict__ adj, const float* __restrict__ invn,
                            __nv_bfloat16* __restrict__ agg16, int n) {
    int lane = threadIdx.x & 31;
    int v = (blockIdx.x * blockDim.x + threadIdx.x) >> 5;
    if (v >= n) return;
    int beg = rowptr[v], end = rowptr[v + 1];
    int d = end - beg;
    float4 a0 = make_float4(0.f, 0.f, 0.f, 0.f);
    float4 a1 = a0, a2 = a0, a3 = a0;
    if (d > 0) {
        int dm1 = d - 1;
        int u[8];
#pragma unroll
        for (int j = 0; j < 8; j++)
            u[j] = __ldg(adj + beg + (j < dm1 ? j : dm1));
        uint2 vv[8];
#pragma unroll
        for (int j = 0; j < 8; j++)
            vv[j] = __ldg(((const uint2*)(h16 + (size_t)u[j] * HH)) + lane);
#pragma unroll
        for (int j = 0; j < 8; j++) {
            if (j < d) {
                float4 f = bf4tof4(vv[j]);
                if ((j & 3) == 0) a0 = f4add(a0, f);
                else if ((j & 3) == 1) a1 = f4add(a1, f);
                else if ((j & 3) == 2) a2 = f4add(a2, f);
                else a3 = f4add(a3, f);
            }
        }
        int i = beg + 8;
        for (; i + 4 <= end; i += 4) {
            int u0 = __ldg(adj + i);
            int u1 = __ldg(adj + i + 1);
            int u2 = __ldg(adj + i + 2);
            int u3 = __ldg(adj + i + 3);
            a0 = f4add(a0, bf4tof4(__ldg(((const uint2*)(h16 + (size_t)u0 * HH)) + lane)));
            a1 = f4add(a1, bf4tof4(__ldg(((const uint2*)(h16 + (size_t)u1 * HH)) + lane)));
            a2 = f4add(a2, bf4tof4(__ldg(((const uint2*)(h16 + (size_t)u2 * HH)) + lane)));
            a3 = f4add(a3, bf4tof4(__ldg(((const uint2*)(h16 + (size_t)u3 * HH)) + lane)));
        }
        for (; i < end; i++) {
            int uu = __ldg(adj + i);
            a0 = f4add(a0, bf4tof4(__ldg(((const uint2*)(h16 + (size_t)uu * HH)) + lane)));
        }
    }
    float4 s = f4add(f4add(a0, a1), f4add(a2, a3));
    float sc = invn[v];
    s.x *= sc; s.y *= sc; s.z *= sc; s.w *= sc;
    ((uint2*)(agg16 + (size_t)v * HH))[lane] = f4tobf4(s);
}

// ---------------- combine (TF32 tensor core, bf16 operands) ----------------
// RES_EMB=1: residual = emb[x[row]] (fp32 hot table), output -> hout16.
// POOL=1:    residual = hprev16[row]; outputs pooled into gsum[batch] (no hout store).
template <int RES_EMB, int POOL>
__global__ void combine_tc_k(const __nv_bfloat16* __restrict__ agg16,
                             const __nv_bfloat16* __restrict__ hprev16,
                             const int* __restrict__ xres, const float* __restrict__ embres,
                             const float* __restrict__ W, const float* __restrict__ bias,
                             const int* __restrict__ batch, float* __restrict__ gsum,
                             __nv_bfloat16* __restrict__ hout16, int n) {
    extern __shared__ float smem[];
    float* As = smem;
    float* Ws = smem + 128 * ASTRIDE;
    int tid  = threadIdx.x;
    int lane = tid & 31;
    int warp = tid >> 5;
    int gid  = lane >> 2;
    int tig  = lane & 3;
    int wm   = warp >> 1;
    int wn   = warp & 1;
    int m0   = blockIdx.x * BM;
    int wm0  = wm * 32;
    int wn0  = wn * 64;

    float acc[2][8][4];
#pragma unroll
    for (int t = 0; t < 2; t++)
#pragma unroll
        for (int j = 0; j < 8; j++)
#pragma unroll
            for (int c = 0; c < 4; c++) acc[t][j][c] = 0.f;

#pragma unroll
    for (int kb = 0; kb < HH; kb += 64) {
        for (int f = tid; f < 128 * 16; f += 256) {
            int m = f >> 4, c4 = f & 15;
            int gm = m0 + m;
            float4 v = make_float4(0.f, 0.f, 0.f, 0.f);
            if (gm < n) {
                uint2 r = __ldg((const uint2*)(agg16 + (size_t)gm * HH + kb) + c4);
                v = bf4tof4(r);
            }
            *(float4*)(As + m * ASTRIDE + c4 * 4) = v;
        }
        for (int f = tid; f < 64 * 32; f += 256) {
            int k = f >> 5, n4 = f & 31;
            float4 v = __ldg((const float4*)(W + (size_t)(kb + k) * HH) + n4);
            v.x = tf32r(v.x); v.y = tf32r(v.y); v.z = tf32r(v.z); v.w = tf32r(v.w);
            *(float4*)(Ws + k * WSTRIDE + n4 * 4) = v;
        }
        __syncthreads();

#pragma unroll
        for (int kk = 0; kk < 64; kk += 8) {
            uint32_t afrag[2][4];
#pragma unroll
            for (int t = 0; t < 2; t++) {
                const float* ab = As + (wm0 + 16 * t + gid) * ASTRIDE + kk + tig;
                afrag[t][0] = __float_as_uint(ab[0]);
                afrag[t][1] = __float_as_uint(ab[8 * ASTRIDE]);
                afrag[t][2] = __float_as_uint(ab[4]);
                afrag[t][3] = __float_as_uint(ab[8 * ASTRIDE + 4]);
            }
#pragma unroll
            for (int j = 0; j < 8; j++) {
                const float* bb = Ws + (kk + tig) * WSTRIDE + wn0 + 8 * j + gid;
                uint32_t b0 = __float_as_uint(bb[0]);
                uint32_t b1 = __float_as_uint(bb[4 * WSTRIDE]);
                mma_tf32(acc[0][j], afrag[0], b0, b1);
                mma_tf32(acc[1][j], afrag[1], b0, b1);
            }
        }
        __syncthreads();
    }

    // ---- pooled-epilogue setup (POOL=1): reuse As region as [NSEG][HH] accumulator ----
    float* poolBuf = smem;
    int batch0 = 0, segCount = 0;
    bool useSmem = false;
    if (POOL) {
        batch0 = __ldg(batch + m0);
        int lastRow = min(m0 + BM, n) - 1;
        segCount = __ldg(batch + lastRow) - batch0 + 1;
        useSmem = (segCount <= NSEG);
        if (useSmem) {
            for (int f = tid; f < segCount * HH; f += 256) poolBuf[f] = 0.f;
        }
        __syncthreads();
    }

    // ---- epilogue: bias + residual + exact GELU ----
#pragma unroll
    for (int t = 0; t < 2; t++) {
#pragma unroll
        for (int half = 0; half < 2; half++) {
            int row = m0 + wm0 + 16 * t + gid + 8 * half;
            if (row >= n) continue;
            const float* hpf = nullptr;
            const __nv_bfloat16* hpb = nullptr;
            if (RES_EMB) {
                hpf = embres + (size_t)__ldg(xres + row) * HH;
            } else {
                hpb = hprev16 + (size_t)row * HH;
            }
            int seg = 0;
            float* gdst = nullptr;
            if (POOL) {
                int b = __ldg(batch + row);
                seg = b - batch0;
                if (!useSmem) gdst = gsum + (size_t)b * HH;
            }
            __nv_bfloat16* op = POOL ? nullptr : (hout16 + (size_t)row * HH);
#pragma unroll
            for (int j = 0; j < 8; j++) {
                int col = wn0 + 8 * j + 2 * tig;
                float2 bv = *(const float2*)(bias + col);
                float2 hr;
                if (RES_EMB) {
                    hr = __ldg((const float2*)(hpf + col));
                } else {
                    __nv_bfloat162 hb = __ldg((const __nv_bfloat162*)(hpb + col));
                    hr = __bfloat1622float2(hb);
                }
                float ox = gelu_exact(acc[t][j][2 * half]     + bv.x + hr.x);
                float oy = gelu_exact(acc[t][j][2 * half + 1] + bv.y + hr.y);
                if (POOL) {
                    if (useSmem) {
                        atomicAdd(&poolBuf[seg * HH + col],     ox);
                        atomicAdd(&poolBuf[seg * HH + col + 1], oy);
                    } else {
                        redAdd2(gdst + col, ox, oy);
                    }
                } else {
                    __nv_bfloat162 ob = __float22bfloat162_rn(make_float2(ox, oy));
                    *(__nv_bfloat162*)(op + col) = ob;
                }
            }
        }
    }

    // ---- flush pooled partials ----
    if (POOL && useSmem) {
        __syncthreads();
        for (int idx = tid; idx < segCount * 32; idx += 256) {
            int s = idx >> 5, c4 = idx & 31;
            float4 v = *(float4*)(poolBuf + s * HH + c4 * 4);
            redAdd4(gsum + (size_t)(batch0 + s) * HH + c4 * 4, v);
        }
    }
}

// ---------------- final head ----------------
__global__ void final_k(const float* __restrict__ gsum, const int* __restrict__ cnt,
                        const float* __restrict__ Wo, const float* __restrict__ bo,
                        const float* __restrict__ gamma, const float* __restrict__ beta,
                        float* __restrict__ out) {
    __shared__ float g[HH];
    __shared__ float rs[8], rq[8];
    int b = blockIdx.x, tid = threadIdx.x;
    if (tid < HH) g[tid] = gsum[(size_t)b * HH + tid] / fmaxf((float)cnt[b], 1.0f);
    __syncthreads();
    float acc = bo[tid];
#pragma unroll 4
    for (int k = 0; k < HH; k++) acc = fmaf(g[k], Wo[k * OUTD + tid], acc);
    float s = acc, q = acc * acc;
#pragma unroll
    for (int o = 16; o; o >>= 1) {
        s += __shfl_xor_sync(0xFFFFFFFFu, s, o);
        q += __shfl_xor_sync(0xFFFFFFFFu, q, o);
    }
    int w = tid >> 5;
    if ((tid & 31) == 0) { rs[w] = s; rq[w] = q; }
    __syncthreads();
    float ts = 0.f, tq = 0.f;
#pragma unroll
    for (int i = 0; i < 8; i++) { ts += rs[i]; tq += rq[i]; }
    float mu  = ts * (1.0f / OUTD);
    float var = tq * (1.0f / OUTD) - mu * mu;
    out[(size_t)b * OUTD + tid] = (acc - mu) * rsqrtf(var + 1e-5f) * gamma[tid] + beta[tid];
}

// ---------------- launch ----------------
extern "C" void kernel_launch(void* const* d_in, const int* in_sizes, int n_in,
                              void* d_out, int out_size) {
    const int* x     = (const int*)d_in[0];
    const int* ei    = (const int*)d_in[1];
    const int* batch = (const int*)d_in[2];
    int off = (n_in >= 13 && in_sizes[3] == 1) ? 4 : 3;
    const float* emb   = (const float*)d_in[off + 0];
    const float* W0    = (const float*)d_in[off + 1];
    const float* b0    = (const float*)d_in[off + 2];
    const float* W1    = (const float*)d_in[off + 3];
    const float* b1    = (const float*)d_in[off + 4];
    const float* Wo    = (const float*)d_in[off + 5];
    const float* bo    = (const float*)d_in[off + 6];
    const float* gamma = (const float*)d_in[off + 7];
    const float* beta  = (const float*)d_in[off + 8];

    int N = in_sizes[0];
    int E = in_sizes[1] / 2;
    int B = out_size / OUTD;

    float *invn, *gsum;
    __nv_bfloat16 *h1, *agg16;
    int *deg, *cur, *rowptr, *scanTmp, *bsum, *adj, *adjT, *cnt;
    cudaGetSymbolAddress((void**)&h1,   g_h1);
    cudaGetSymbolAddress((void**)&agg16, g_agg16);
    cudaGetSymbolAddress((void**)&invn, g_invn);
    cudaGetSymbolAddress((void**)&gsum, g_gsum);
    cudaGetSymbolAddress((void**)&deg,  g_deg);
    cudaGetSymbolAddress((void**)&cur,  g_cur);
    cudaGetSymbolAddress((void**)&rowptr, g_rowptr);
    cudaGetSymbolAddress((void**)&scanTmp, g_scanTmp);
    cudaGetSymbolAddress((void**)&bsum, g_bsum);
    cudaGetSymbolAddress((void**)&adj,  g_adj);
    cudaGetSymbolAddress((void**)&adjT, g_adjT);
    cudaGetSymbolAddress((void**)&cnt,  g_cnt);

    int smem_tc = (128 * ASTRIDE + 64 * WSTRIDE) * 4;   // 69632 bytes
    cudaFuncSetAttribute((const void*)combine_tc_k<1,0>, cudaFuncAttributeMaxDynamicSharedMemorySize, smem_tc);
    cudaFuncSetAttribute((const void*)combine_tc_k<0,1>, cudaFuncAttributeMaxDynamicSharedMemorySize, smem_tc);

    const int* src = ei;
    const int* dst = ei + E;

    int cblk = (N + BM - 1) / BM;
    int nscan = (N + SCAN_B - 1) / SCAN_B;

    // init + CSR build
    init_k<<<256, 256>>>(deg, cur, cnt, gsum, N, B);
    deg_k<<<(E + 255) / 256, 256>>>(src, dst, deg, E);
    scan1_k<<<nscan, SCAN_B>>>(deg, scanTmp, bsum, N);
    scan2_k<<<1, 1024>>>(bsum, nscan);
    scan3_k<<<nscan, SCAN_B>>>(deg, scanTmp, bsum, batch, rowptr, invn, cnt, N, 2 * E);
    fill_k<<<(E + 255) / 256, 256>>>(src, dst, x, rowptr, cur, adj, adjT, E);

    // layer 1: aggregate from hot emb table -> bf16 agg; combine -> bf16 h1
    aggregate1_k<<<(N * 32 + 255) / 256, 256>>>(emb, rowptr, adjT, invn, agg16, N);
    combine_tc_k<1,0><<<cblk, 256, smem_tc>>>(agg16, nullptr, x, emb, W0, b0,
                                              nullptr, nullptr, h1, N);

    // layer 2: bf16 gather -> bf16 agg; combine with fused segment pooling (no h2 store)
    aggregate_k<<<(N * 32 + 255) / 256, 256>>>(h1, rowptr, adj, invn, agg16, N);
    combine_tc_k<0,1><<<cblk, 256, smem_tc>>>(agg16, h1, nullptr, nullptr, W1, b1,
                                              batch, gsum, nullptr, N);

    // head
    final_k<<<B, 256>>>(gsum, cnt, Wo, bo, gamma, beta, (float*)d_out);
}

// round 14
// speedup vs baseline: 1.1114x; 1.1114x over previous
#include <cuda_runtime.h>
#include <cuda_bf16.h>
#include <math.h>
#include <stdint.h>

#define NN   200000
#define EE   600000
#define HH   128
#define OUTD 256
#define BMAXG 1024
#define BM   128

// tf32 GEMM tile params
#define ASTRIDE 68     // 64-col chunk + 4 pad
#define WSTRIDE 136    // 128-col + 8 pad

// ---------------- scratch (device globals; no allocation) ----------------
__device__ __nv_bfloat16 g_h1  [(size_t)NN * HH];   // layer-1 output (51.2 MB)
__device__ __nv_bfloat16 g_h2  [(size_t)NN * HH];   // layer-2 output (51.2 MB)
__device__ __nv_bfloat16 g_agg16[(size_t)NN * HH];  // aggregation buffer (51.2 MB)
__device__ int   g_deg [NN];
__device__ int   g_cur [NN];
__device__ int   g_rowptr[NN];
__device__ int2  g_adjP[2 * EE];                    // (.x = neighbor id, .y = neighbor type)
__device__ int   g_ctr[1];
__device__ float g_invn[NN];
__device__ float g_gsum[BMAXG * HH];
__device__ int   g_cnt [BMAXG];

// ---------------- helpers ----------------
__device__ __forceinline__ void redAdd4(float* p, float4 v) {
    asm volatile("red.global.add.v4.f32 [%0], {%1,%2,%3,%4};"
                 :: "l"(p), "f"(v.x), "f"(v.y), "f"(v.z), "f"(v.w) : "memory");
}
__device__ __forceinline__ float gelu_exact(float v) {
    return 0.5f * v * (1.0f + erff(v * 0.70710678118654752f));
}
__device__ __forceinline__ float4 f4add(float4 a, float4 b) {
    return make_float4(a.x + b.x, a.y + b.y, a.z + b.z, a.w + b.w);
}
__device__ __forceinline__ float tf32r(float x) {
    float y;
    asm("cvt.rna.tf32.f32 %0, %1;" : "=f"(y) : "f"(x));
    return y;
}
__device__ __forceinline__ float4 bf4tof4(uint2 r) {
    float4 f;
    f.x = __uint_as_float(r.x << 16);
    f.y = __uint_as_float(r.x & 0xFFFF0000u);
    f.z = __uint_as_float(r.y << 16);
    f.w = __uint_as_float(r.y & 0xFFFF0000u);
    return f;
}
__device__ __forceinline__ uint2 f4tobf4(float4 s) {
    __nv_bfloat162 h0 = __float22bfloat162_rn(make_float2(s.x, s.y));
    __nv_bfloat162 h1 = __float22bfloat162_rn(make_float2(s.z, s.w));
    uint2 o;
    o.x = *(uint32_t*)&h0;
    o.y = *(uint32_t*)&h1;
    return o;
}
__device__ __forceinline__ void mma_tf32(float* c, const uint32_t* a, uint32_t b0, uint32_t b1) {
    asm volatile(
        "mma.sync.aligned.m16n8k8.row.col.f32.tf32.tf32.f32 "
        "{%0,%1,%2,%3}, {%4,%5,%6,%7}, {%8,%9}, {%0,%1,%2,%3};"
        : "+f"(c[0]), "+f"(c[1]), "+f"(c[2]), "+f"(c[3])
        : "r"(a[0]), "r"(a[1]), "r"(a[2]), "r"(a[3]), "r"(b0), "r"(b1));
}

// ---------------- fused init ----------------
__global__ void init_k(int* __restrict__ deg, int* __restrict__ cur,
                       int* __restrict__ cnt, float* __restrict__ gsum,
                       int* __restrict__ ctr, int n, int b) {
    int i = blockIdx.x * blockDim.x + threadIdx.x;
    int s = gridDim.x * blockDim.x;
    for (int f = i; f < n; f += s) { deg[f] = 0; cur[f] = 0; }
    int g = b * HH;
    for (int f = i; f < g; f += s) gsum[f] = 0.f;
    for (int f = i; f < b; f += s) cnt[f] = 0;
    if (i == 0) ctr[0] = 0;
}

// ---------------- degree ----------------
__global__ void deg_k(const int* __restrict__ src, const int* __restrict__ dst,
                      int* __restrict__ deg, int E) {
    int e = blockIdx.x * blockDim.x + threadIdx.x;
    if (e < E) {
        atomicAdd(&deg[src[e]], 1);
        atomicAdd(&deg[dst[e]], 1);
    }
}

// ---------------- region assignment (replaces 3-kernel scan) ----------------
// Warp-scan degrees; one atomicAdd per warp bumps the global cursor.
// Region ORDER in adjP is arbitrary — correctness only needs [rowptr[v], rowptr[v]+deg[v]).
__global__ void assign_k(const int* __restrict__ deg, const int* __restrict__ batch,
                         int* __restrict__ rowptr, float* __restrict__ invn,
                         int* __restrict__ cnt, int* __restrict__ ctr, int n) {
    int v = blockIdx.x * blockDim.x + threadIdx.x;
    int lane = threadIdx.x & 31;
    int d = (v < n) ? __ldg(deg + v) : 0;
    int incl = d;
#pragma unroll
    for (int o = 1; o < 32; o <<= 1) {
        int t = __shfl_up_sync(0xFFFFFFFFu, incl, o);
        if (lane >= o) incl += t;
    }
    int base = 0;
    if (lane == 31) base = atomicAdd(ctr, incl);
    base = __shfl_sync(0xFFFFFFFFu, base, 31);
    if (v < n) {
        rowptr[v] = base + incl - d;
        invn[v] = rsqrtf(fmaxf((float)d, 1.0f));
        atomicAdd(&cnt[__ldg(batch + v)], 1);
    }
}

// ---------------- CSR fill (packed int2: neighbor id + neighbor type) ----------------
__global__ void fill_k(const int* __restrict__ src, const int* __restrict__ dst,
                       const int* __restrict__ x, const int* __restrict__ rowptr,
                       int* __restrict__ cur, int2* __restrict__ adjP, int E) {
    int e = blockIdx.x * blockDim.x + threadIdx.x;
    if (e < E) {
        int s = src[e], d = dst[e];
        int xs = __ldg(x + s), xd = __ldg(x + d);
        int p = atomicAdd(&cur[d], 1);
        adjP[rowptr[d] + p] = make_int2(s, xs);
        int q = atomicAdd(&cur[s], 1);
        adjP[rowptr[s] + q] = make_int2(d, xd);
    }
}

// ---------------- layer-1 aggregation: neighbor type -> hot 153KB emb table ----------------
__global__ void aggregate1_k(const float* __restrict__ emb, const int* __restrict__ rowptr,
                             const int* __restrict__ deg, const int2* __restrict__ adjP,
                             const float* __restrict__ invn,
                             __nv_bfloat16* __restrict__ agg16, int n) {
    int lane = threadIdx.x & 31;
    int v = (blockIdx.x * blockDim.x + threadIdx.x) >> 5;
    if (v >= n) return;
    int beg = __ldg(rowptr + v);
    int end = beg + __ldg(deg + v);
    float4 a0 = make_float4(0.f, 0.f, 0.f, 0.f);
    float4 a1 = a0, a2 = a0, a3 = a0;
    int i = beg;
    for (; i + 4 <= end; i += 4) {
        int t0 = __ldg(adjP + i).y;
        int t1 = __ldg(adjP + i + 1).y;
        int t2 = __ldg(adjP + i + 2).y;
        int t3 = __ldg(adjP + i + 3).y;
        a0 = f4add(a0, __ldg(((const float4*)(emb + (size_t)t0 * HH)) + lane));
        a1 = f4add(a1, __ldg(((const float4*)(emb + (size_t)t1 * HH)) + lane));
        a2 = f4add(a2, __ldg(((const float4*)(emb + (size_t)t2 * HH)) + lane));
        a3 = f4add(a3, __ldg(((const float4*)(emb + (size_t)t3 * HH)) + lane));
    }
    for (; i < end; i++) {
        int t = __ldg(adjP + i).y;
        a0 = f4add(a0, __ldg(((const float4*)(emb + (size_t)t * HH)) + lane));
    }
    float4 s = f4add(f4add(a0, a1), f4add(a2, a3));
    float sc = invn[v];
    s.x *= sc; s.y *= sc; s.z *= sc; s.w *= sc;
    ((uint2*)(agg16 + (size_t)v * HH))[lane] = f4tobf4(s);
}

// ---------------- layer-2 aggregation: flat 8-wide bf16 gather ----------------
__global__ void aggregate_k(const __nv_bfloat16* __restrict__ h16, const int* __restrict__ rowptr,
                            const int* __restrict__ deg, const int2* __restrict__ adjP,
                            const float* __restrict__ invn,
                            __nv_bfloat16* __restrict__ agg16, int n) {
    int lane = threadIdx.x & 31;
    int v = (blockIdx.x * blockDim.x + threadIdx.x) >> 5;
    if (v >= n) return;
    int beg = __ldg(rowptr + v);
    int d = __ldg(deg + v);
    int end = beg + d;
    float4 a0 = make_float4(0.f, 0.f, 0.f, 0.f);
    float4 a1 = a0, a2 = a0, a3 = a0;
    if (d > 0) {
        int dm1 = d - 1;
        int u[8];
#pragma unroll
        for (int j = 0; j < 8; j++)
            u[j] = __ldg(adjP + beg + (j < dm1 ? j : dm1)).x;
        uint2 vv[8];
#pragma unroll
        for (int j = 0; j < 8; j++)
            vv[j] = __ldg(((const uint2*)(h16 + (size_t)u[j] * HH)) + lane);
#pragma unroll
        for (int j = 0; j < 8; j++) {
            if (j < d) {
                float4 f = bf4tof4(vv[j]);
                if ((j & 3) == 0) a0 = f4add(a0, f);
                else if ((j & 3) == 1) a1 = f4add(a1, f);
                else if ((j & 3) == 2) a2 = f4add(a2, f);
                else a3 = f4add(a3, f);
            }
        }
        int i = beg + 8;
        for (; i + 4 <= end; i += 4) {
            int u0 = __ldg(adjP + i).x;
            int u1 = __ldg(adjP + i + 1).x;
            int u2 = __ldg(adjP + i + 2).x;
            int u3 = __ldg(adjP + i + 3).x;
            a0 = f4add(a0, bf4tof4(__ldg(((const uint2*)(h16 + (size_t)u0 * HH)) + lane)));
            a1 = f4add(a1, bf4tof4(__ldg(((const uint2*)(h16 + (size_t)u1 * HH)) + lane)));
            a2 = f4add(a2, bf4tof4(__ldg(((const uint2*)(h16 + (size_t)u2 * HH)) + lane)));
            a3 = f4add(a3, bf4tof4(__ldg(((const uint2*)(h16 + (size_t)u3 * HH)) + lane)));
        }
        for (; i < end; i++) {
            int uu = __ldg(adjP + i).x;
            a0 = f4add(a0, bf4tof4(__ldg(((const uint2*)(h16 + (size_t)uu * HH)) + lane)));
        }
    }
    float4 s = f4add(f4add(a0, a1), f4add(a2, a3));
    float sc = invn[v];
    s.x *= sc; s.y *= sc; s.z *= sc; s.w *= sc;
    ((uint2*)(agg16 + (size_t)v * HH))[lane] = f4tobf4(s);
}

// ---------------- combine (TF32 tensor core, bf16 operands/outputs) ----------------
// RES_EMB=1: residual = emb[x[row]] (fp32 hot table). RES_EMB=0: residual = hprev16[row] (bf16).
template <int RES_EMB>
__global__ void combine_tc_k(const __nv_bfloat16* __restrict__ agg16,
                             const __nv_bfloat16* __restrict__ hprev16,
                             const int* __restrict__ xres, const float* __restrict__ embres,
                             const float* __restrict__ W, const float* __restrict__ bias,
                             __nv_bfloat16* __restrict__ hout16, int n) {
    extern __shared__ float smem[];
    float* As = smem;
    float* Ws = smem + 128 * ASTRIDE;
    int tid  = threadIdx.x;
    int lane = tid & 31;
    int warp = tid >> 5;
    int gid  = lane >> 2;
    int tig  = lane & 3;
    int wm   = warp >> 1;
    int wn   = warp & 1;
    int m0   = blockIdx.x * BM;
    int wm0  = wm * 32;
    int wn0  = wn * 64;

    float acc[2][8][4];
#pragma unroll
    for (int t = 0; t < 2; t++)
#pragma unroll
        for (int j = 0; j < 8; j++)
#pragma unroll
            for (int c = 0; c < 4; c++) acc[t][j][c] = 0.f;

#pragma unroll
    for (int kb = 0; kb < HH; kb += 64) {
        for (int f = tid; f < 128 * 16; f += 256) {
            int m = f >> 4, c4 = f & 15;
            int gm = m0 + m;
            float4 v = make_float4(0.f, 0.f, 0.f, 0.f);
            if (gm < n) {
                uint2 r = __ldg((const uint2*)(agg16 + (size_t)gm * HH + kb) + c4);
                v = bf4tof4(r);
            }
            *(float4*)(As + m * ASTRIDE + c4 * 4) = v;
        }
        for (int f = tid; f < 64 * 32; f += 256) {
            int k = f >> 5, n4 = f & 31;
            float4 v = __ldg((const float4*)(W + (size_t)(kb + k) * HH) + n4);
            v.x = tf32r(v.x); v.y = tf32r(v.y); v.z = tf32r(v.z); v.w = tf32r(v.w);
            *(float4*)(Ws + k * WSTRIDE + n4 * 4) = v;
        }
        __syncthreads();

#pragma unroll
        for (int kk = 0; kk < 64; kk += 8) {
            uint32_t afrag[2][4];
#pragma unroll
            for (int t = 0; t < 2; t++) {
                const float* ab = As + (wm0 + 16 * t + gid) * ASTRIDE + kk + tig;
                afrag[t][0] = __float_as_uint(ab[0]);
                afrag[t][1] = __float_as_uint(ab[8 * ASTRIDE]);
                afrag[t][2] = __float_as_uint(ab[4]);
                afrag[t][3] = __float_as_uint(ab[8 * ASTRIDE + 4]);
            }
#pragma unroll
            for (int j = 0; j < 8; j++) {
                const float* bb = Ws + (kk + tig) * WSTRIDE + wn0 + 8 * j + gid;
                uint32_t b0 = __float_as_uint(bb[0]);
                uint32_t b1 = __float_as_uint(bb[4 * WSTRIDE]);
                mma_tf32(acc[0][j], afrag[0], b0, b1);
                mma_tf32(acc[1][j], afrag[1], b0, b1);
            }
        }
        __syncthreads();
    }

    // epilogue: bias + residual + exact GELU -> bf16 store
#pragma unroll
    for (int t = 0; t < 2; t++) {
#pragma unroll
        for (int half = 0; half < 2; half++) {
            int row = m0 + wm0 + 16 * t + gid + 8 * half;
            if (row >= n) continue;
            const float* hpf = nullptr;
            const __nv_bfloat16* hpb = nullptr;
            if (RES_EMB) {
                hpf = embres + (size_t)__ldg(xres + row) * HH;
            } else {
                hpb = hprev16 + (size_t)row * HH;
            }
            __nv_bfloat16* op = hout16 + (size_t)row * HH;
#pragma unroll
            for (int j = 0; j < 8; j++) {
                int col = wn0 + 8 * j + 2 * tig;
                float2 bv = *(const float2*)(bias + col);
                float2 hr;
                if (RES_EMB) {
                    hr = __ldg((const float2*)(hpf + col));
                } else {
                    __nv_bfloat162 hb = __ldg((const __nv_bfloat162*)(hpb + col));
                    hr = __bfloat1622float2(hb);
                }
                float2 o;
                o.x = gelu_exact(acc[t][j][2 * half]     + bv.x + hr.x);
                o.y = gelu_exact(acc[t][j][2 * half + 1] + bv.y + hr.y);
                __nv_bfloat162 ob = __float22bfloat162_rn(o);
                *(__nv_bfloat162*)(op + col) = ob;
            }
        }
    }
}

// ---------------- pooling (bf16 input, fp32 reduction) ----------------
__global__ void pool_k(const __nv_bfloat16* __restrict__ h16, const int* __restrict__ batch,
                       float* __restrict__ gsum, int n) {
    int gt = blockIdx.x * blockDim.x + threadIdx.x;
    int nd = gt >> 5, lane = gt & 31;
    if (nd >= n) return;
    int b = batch[nd];
    uint2 r = ((const uint2*)(h16 + (size_t)nd * HH))[lane];
    redAdd4(gsum + (size_t)b * HH + lane * 4, bf4tof4(r));
}

// ---------------- final head ----------------
__global__ void final_k(const float* __restrict__ gsum, const int* __restrict__ cnt,
                        const float* __restrict__ Wo, const float* __restrict__ bo,
                        const float* __restrict__ gamma, const float* __restrict__ beta,
                        float* __restrict__ out) {
    __shared__ float g[HH];
    __shared__ float rs[8], rq[8];
    int b = blockIdx.x, tid = threadIdx.x;
    if (tid < HH) g[tid] = gsum[(size_t)b * HH + tid] / fmaxf((float)cnt[b], 1.0f);
    __syncthreads();
    float acc = bo[tid];
#pragma unroll 4
    for (int k = 0; k < HH; k++) acc = fmaf(g[k], Wo[k * OUTD + tid], acc);
    float s = acc, q = acc * acc;
#pragma unroll
    for (int o = 16; o; o >>= 1) {
        s += __shfl_xor_sync(0xFFFFFFFFu, s, o);
        q += __shfl_xor_sync(0xFFFFFFFFu, q, o);
    }
    int w = tid >> 5;
    if ((tid & 31) == 0) { rs[w] = s; rq[w] = q; }
    __syncthreads();
    float ts = 0.f, tq = 0.f;
#pragma unroll
    for (int i = 0; i < 8; i++) { ts += rs[i]; tq += rq[i]; }
    float mu  = ts * (1.0f / OUTD);
    float var = tq * (1.0f / OUTD) - mu * mu;
    out[(size_t)b * OUTD + tid] = (acc - mu) * rsqrtf(var + 1e-5f) * gamma[tid] + beta[tid];
}

// ---------------- launch ----------------
extern "C" void kernel_launch(void* const* d_in, const int* in_sizes, int n_in,
                              void* d_out, int out_size) {
    const int* x     = (const int*)d_in[0];
    const int* ei    = (const int*)d_in[1];
    const int* batch = (const int*)d_in[2];
    int off = (n_in >= 13 && in_sizes[3] == 1) ? 4 : 3;
    const float* emb   = (const float*)d_in[off + 0];
    const float* W0    = (const float*)d_in[off + 1];
    const float* b0    = (const float*)d_in[off + 2];
    const float* W1    = (const float*)d_in[off + 3];
    const float* b1    = (const float*)d_in[off + 4];
    const float* Wo    = (const float*)d_in[off + 5];
    const float* bo    = (const float*)d_in[off + 6];
    const float* gamma = (const float*)d_in[off + 7];
    const float* beta  = (const float*)d_in[off + 8];

    int N = in_sizes[0];
    int E = in_sizes[1] / 2;
    int B = out_size / OUTD;

    float *invn, *gsum;
    __nv_bfloat16 *h1, *h2, *agg16;
    int *deg, *cur, *rowptr, *cnt, *ctr;
    int2 *adjP;
    cudaGetSymbolAddress((void**)&h1,   g_h1);
    cudaGetSymbolAddress((void**)&h2,   g_h2);
    cudaGetSymbolAddress((void**)&agg16, g_agg16);
    cudaGetSymbolAddress((void**)&invn, g_invn);
    cudaGetSymbolAddress((void**)&gsum, g_gsum);
    cudaGetSymbolAddress((void**)&deg,  g_deg);
    cudaGetSymbolAddress((void**)&cur,  g_cur);
    cudaGetSymbolAddress((void**)&rowptr, g_rowptr);
    cudaGetSymbolAddress((void**)&adjP, g_adjP);
    cudaGetSymbolAddress((void**)&ctr,  g_ctr);
    cudaGetSymbolAddress((void**)&cnt,  g_cnt);

    int smem_tc = (128 * ASTRIDE + 64 * WSTRIDE) * 4;   // 69632 bytes
    cudaFuncSetAttribute((const void*)combine_tc_k<1>, cudaFuncAttributeMaxDynamicSharedMemorySize, smem_tc);
    cudaFuncSetAttribute((const void*)combine_tc_k<0>, cudaFuncAttributeMaxDynamicSharedMemorySize, smem_tc);

    const int* src = ei;
    const int* dst = ei + E;

    int gthr = N * 32;
    int gblk = (gthr + 255) / 256;
    int cblk = (N + BM - 1) / BM;

    // init + CSR build (no scan: warp-aggregated atomic region assignment)
    init_k<<<256, 256>>>(deg, cur, cnt, gsum, ctr, N, B);
    deg_k<<<(E + 255) / 256, 256>>>(src, dst, deg, E);
    assign_k<<<(N + 255) / 256, 256>>>(deg, batch, rowptr, invn, cnt, ctr, N);
    fill_k<<<(E + 255) / 256, 256>>>(src, dst, x, rowptr, cur, adjP, E);

    // layer 1: aggregate from hot emb table -> bf16 agg; combine -> bf16 h1
    aggregate1_k<<<(N * 32 + 255) / 256, 256>>>(emb, rowptr, deg, adjP, invn, agg16, N);
    combine_tc_k<1><<<cblk, 256, smem_tc>>>(agg16, nullptr, x, emb, W0, b0, h1, N);

    // layer 2: bf16 gather -> bf16 agg; combine (bf16 residual) -> bf16 h2
    aggregate_k<<<(N * 32 + 255) / 256, 256>>>(h1, rowptr, deg, adjP, invn, agg16, N);
    combine_tc_k<0><<<cblk, 256, smem_tc>>>(agg16, h1, nullptr, nullptr, W1, b1, h2, N);

    // pool + head
    pool_k<<<gblk, 256>>>(h2, batch, gsum, N);
    final_k<<<B, 256>>>(gsum, cnt, Wo, bo, gamma, beta, (float*)d_out);
}

// round 15
// speedup vs baseline: 1.4424x; 1.2978x over previous
#include <cuda_runtime.h>
#include <cuda_bf16.h>
#include <math.h>
#include <stdint.h>

#define NN   200000
#define EE   600000
#define HH   128
#define OUTD 256
#define BMAXG 1024
#define BM   128

// tf32 GEMM tile params
#define ASTRIDE 68     // 64-col chunk + 4 pad
#define WSTRIDE 136    // 128-col + 8 pad

// ---------------- scratch (device globals; no allocation) ----------------
__device__ __nv_bfloat16 g_h1  [(size_t)NN * HH];   // layer-1 output (51.2 MB)
__device__ __nv_bfloat16 g_h2  [(size_t)NN * HH];   // layer-2 output (51.2 MB)
__device__ __nv_bfloat16 g_agg16[(size_t)NN * HH];  // aggregation buffer (51.2 MB)
__device__ int   g_deg [NN];
__device__ int   g_cur [NN];
__device__ int   g_rowptr[NN];
__device__ int2  g_adjP[2 * EE];                    // (.x = neighbor id, .y = neighbor type)
__device__ int   g_ctr[1];
__device__ float g_invn[NN];
__device__ float g_gsum[BMAXG * HH];
// ---------------- helpers ----------------
__device__ __forceinline__ float gelu_exact(float v) {
    return 0.5f * v * (1.0f + erff(v * 0.70710678118654752f));
}
__device__ __forceinline__ float4 f4add(float4 a, float4 b) {
    return make_float4(a.x + b.x, a.y + b.y, a.z + b.z, a.w + b.w);
}
__device__ __forceinline__ float tf32r(float x) {
    float y;
    asm("cvt.rna.tf32.f32 %0, %1;" : "=f"(y) : "f"(x));
    return y;
}
__device__ __forceinline__ float4 bf4tof4(uint2 r) {
    float4 f;
    f.x = __uint_as_float(r.x << 16);
    f.y = __uint_as_float(r.x & 0xFFFF0000u);
    f.z = __uint_as_float(r.y << 16);
    f.w = __uint_as_float(r.y & 0xFFFF0000u);
    return f;
}
__device__ __forceinline__ uint2 f4tobf4(float4 s) {
    __nv_bfloat162 h0 = __float22bfloat162_rn(make_float2(s.x, s.y));
    __nv_bfloat162 h1 = __float22bfloat162_rn(make_float2(s.z, s.w));
    uint2 o;
    o.x = *(uint32_t*)&h0;
    o.y = *(uint32_t*)&h1;
    return o;
}
__device__ __forceinline__ void mma_tf32(float* c, const uint32_t* a, uint32_t b0, uint32_t b1) {
    asm volatile(
        "mma.sync.aligned.m16n8k8.row.col.f32.tf32.tf32.f32 "
        "{%0,%1,%2,%3}, {%4,%5,%6,%7}, {%8,%9}, {%0,%1,%2,%3};"
        : "+f"(c[0]), "+f"(c[1]), "+f"(c[2]), "+f"(c[3])
        : "r"(a[0]), "r"(a[1]), "r"(a[2]), "r"(a[3]), "r"(b0), "r"(b1));
}

// ---------------- fused init ----------------
__global__ void init_k(int* __restrict__ deg, int* __restrict__ cur,
                       int* __restrict__ ctr, int n) {
    int i = blockIdx.x * blockDim.x + threadIdx.x;
    int s = gridDim.x * blockDim.x;
    for (int f = i; f < n; f += s) { deg[f] = 0; cur[f] = 0; }
    if (i == 0) ctr[0] = 0;
}

// ---------------- degree ----------------
__global__ void deg_k(const int* __restrict__ src, const int* __restrict__ dst,
                      int* __restrict__ deg, int E) {
    int e = blockIdx.x * blockDim.x + threadIdx.x;
    if (e < E) {
        atomicAdd(&deg[src[e]], 1);
        atomicAdd(&deg[dst[e]], 1);
    }
}

// ---------------- region assignment (warp-scan + one atomic per warp) ----------------
__global__ void assign_k(const int* __restrict__ deg, int* __restrict__ rowptr,
                         float* __restrict__ invn, int* __restrict__ ctr, int n) {
    int v = blockIdx.x * blockDim.x + threadIdx.x;
    int lane = threadIdx.x & 31;
    int d = (v < n) ? __ldg(deg + v) : 0;
    int incl = d;
#pragma unroll
    for (int o = 1; o < 32; o <<= 1) {
        int t = __shfl_up_sync(0xFFFFFFFFu, incl, o);
        if (lane >= o) incl += t;
    }
    int base = 0;
    if (lane == 31) base = atomicAdd(ctr, incl);
    base = __shfl_sync(0xFFFFFFFFu, base, 31);
    if (v < n) {
        rowptr[v] = base + incl - d;
        invn[v] = rsqrtf(fmaxf((float)d, 1.0f));
    }
}

// ---------------- CSR fill (packed int2: neighbor id + neighbor type) ----------------
__global__ void fill_k(const int* __restrict__ src, const int* __restrict__ dst,
                       const int* __restrict__ x, const int* __restrict__ rowptr,
                       int* __restrict__ cur, int2* __restrict__ adjP, int E) {
    int e = blockIdx.x * blockDim.x + threadIdx.x;
    if (e < E) {
        int s = src[e], d = dst[e];
        int xs = __ldg(x + s), xd = __ldg(x + d);
        int p = atomicAdd(&cur[d], 1);
        adjP[rowptr[d] + p] = make_int2(s, xs);
        int q = atomicAdd(&cur[s], 1);
        adjP[rowptr[s] + q] = make_int2(d, xd);
    }
}

// ---------------- layer-1 aggregation: neighbor type -> hot 153KB emb table ----------------
__global__ void aggregate1_k(const float* __restrict__ emb, const int* __restrict__ rowptr,
                             const int* __restrict__ deg, const int2* __restrict__ adjP,
                             const float* __restrict__ invn,
                             __nv_bfloat16* __restrict__ agg16, int n) {
    int lane = threadIdx.x & 31;
    int v = (blockIdx.x * blockDim.x + threadIdx.x) >> 5;
    if (v >= n) return;
    int beg = __ldg(rowptr + v);
    int end = beg + __ldg(deg + v);
    float4 a0 = make_float4(0.f, 0.f, 0.f, 0.f);
    float4 a1 = a0, a2 = a0, a3 = a0;
    int i = beg;
    for (; i + 4 <= end; i += 4) {
        int t0 = __ldg(adjP + i).y;
        int t1 = __ldg(adjP + i + 1).y;
        int t2 = __ldg(adjP + i + 2).y;
        int t3 = __ldg(adjP + i + 3).y;
        a0 = f4add(a0, __ldg(((const float4*)(emb + (size_t)t0 * HH)) + lane));
        a1 = f4add(a1, __ldg(((const float4*)(emb + (size_t)t1 * HH)) + lane));
        a2 = f4add(a2, __ldg(((const float4*)(emb + (size_t)t2 * HH)) + lane));
        a3 = f4add(a3, __ldg(((const float4*)(emb + (size_t)t3 * HH)) + lane));
    }
    for (; i < end; i++) {
        int t = __ldg(adjP + i).y;
        a0 = f4add(a0, __ldg(((const float4*)(emb + (size_t)t * HH)) + lane));
    }
    float4 s = f4add(f4add(a0, a1), f4add(a2, a3));
    float sc = invn[v];
    s.x *= sc; s.y *= sc; s.z *= sc; s.w *= sc;
    ((uint2*)(agg16 + (size_t)v * HH))[lane] = f4tobf4(s);
}

// ---------------- layer-2 aggregation: flat 8-wide bf16 gather ----------------
__global__ void aggregate_k(const __nv_bfloat16* __restrict__ h16, const int* __restrict__ rowptr,
                            const int* __restrict__ deg, const int2* __restrict__ adjP,
                            const float* __restrict__ invn,
                            __nv_bfloat16* __restrict__ agg16, int n) {
    int lane = threadIdx.x & 31;
    int v = (blockIdx.x * blockDim.x + threadIdx.x) >> 5;
    if (v >= n) return;
    int beg = __ldg(rowptr + v);
    int d = __ldg(deg + v);
    int end = beg + d;
    float4 a0 = make_float4(0.f, 0.f, 0.f, 0.f);
    float4 a1 = a0, a2 = a0, a3 = a0;
    if (d > 0) {
        int dm1 = d - 1;
        int u[8];
#pragma unroll
        for (int j = 0; j < 8; j++)
            u[j] = __ldg(adjP + beg + (j < dm1 ? j : dm1)).x;
        uint2 vv[8];
#pragma unroll
        for (int j = 0; j < 8; j++)
            vv[j] = __ldg(((const uint2*)(h16 + (size_t)u[j] * HH)) + lane);
#pragma unroll
        for (int j = 0; j < 8; j++) {
            if (j < d) {
                float4 f = bf4tof4(vv[j]);
                if ((j & 3) == 0) a0 = f4add(a0, f);
                else if ((j & 3) == 1) a1 = f4add(a1, f);
                else if ((j & 3) == 2) a2 = f4add(a2, f);
                else a3 = f4add(a3, f);
            }
        }
        int i = beg + 8;
        for (; i + 4 <= end; i += 4) {
            int u0 = __ldg(adjP + i).x;
            int u1 = __ldg(adjP + i + 1).x;
            int u2 = __ldg(adjP + i + 2).x;
            int u3 = __ldg(adjP + i + 3).x;
            a0 = f4add(a0, bf4tof4(__ldg(((const uint2*)(h16 + (size_t)u0 * HH)) + lane)));
            a1 = f4add(a1, bf4tof4(__ldg(((const uint2*)(h16 + (size_t)u1 * HH)) + lane)));
            a2 = f4add(a2, bf4tof4(__ldg(((const uint2*)(h16 + (size_t)u2 * HH)) + lane)));
            a3 = f4add(a3, bf4tof4(__ldg(((const uint2*)(h16 + (size_t)u3 * HH)) + lane)));
        }
        for (; i < end; i++) {
            int uu = __ldg(adjP + i).x;
            a0 = f4add(a0, bf4tof4(__ldg(((const uint2*)(h16 + (size_t)uu * HH)) + lane)));
        }
    }
    float4 s = f4add(f4add(a0, a1), f4add(a2, a3));
    float sc = invn[v];
    s.x *= sc; s.y *= sc; s.z *= sc; s.w *= sc;
    ((uint2*)(agg16 + (size_t)v * HH))[lane] = f4tobf4(s);
}

// ---------------- combine (TF32 tensor core, bf16 operands/outputs) ----------------
template <int RES_EMB>
__global__ void combine_tc_k(const __nv_bfloat16* __restrict__ agg16,
                             const __nv_bfloat16* __restrict__ hprev16,
                             const int* __restrict__ xres, const float* __restrict__ embres,
                             const float* __restrict__ W, const float* __restrict__ bias,
                             __nv_bfloat16* __restrict__ hout16, int n) {
    extern __shared__ float smem[];
    float* As = smem;
    float* Ws = smem + 128 * ASTRIDE;
    int tid  = threadIdx.x;
    int lane = tid & 31;
    int warp = tid >> 5;
    int gid  = lane >> 2;
    int tig  = lane & 3;
    int wm   = warp >> 1;
    int wn   = warp & 1;
    int m0   = blockIdx.x * BM;
    int wm0  = wm * 32;
    int wn0  = wn * 64;

    float acc[2][8][4];
#pragma unroll
    for (int t = 0; t < 2; t++)
#pragma unroll
        for (int j = 0; j < 8; j++)
#pragma unroll
            for (int c = 0; c < 4; c++) acc[t][j][c] = 0.f;

#pragma unroll
    for (int kb = 0; kb < HH; kb += 64) {
        for (int f = tid; f < 128 * 16; f += 256) {
            int m = f >> 4, c4 = f & 15;
            int gm = m0 + m;
            float4 v = make_float4(0.f, 0.f, 0.f, 0.f);
            if (gm < n) {
                uint2 r = __ldg((const uint2*)(agg16 + (size_t)gm * HH + kb) + c4);
                v = bf4tof4(r);
            }
            *(float4*)(As + m * ASTRIDE + c4 * 4) = v;
        }
        for (int f = tid; f < 64 * 32; f += 256) {
            int k = f >> 5, n4 = f & 31;
            float4 v = __ldg((const float4*)(W + (size_t)(kb + k) * HH) + n4);
            v.x = tf32r(v.x); v.y = tf32r(v.y); v.z = tf32r(v.z); v.w = tf32r(v.w);
            *(float4*)(Ws + k * WSTRIDE + n4 * 4) = v;
        }
        __syncthreads();

#pragma unroll
        for (int kk = 0; kk < 64; kk += 8) {
            uint32_t afrag[2][4];
#pragma unroll
            for (int t = 0; t < 2; t++) {
                const float* ab = As + (wm0 + 16 * t + gid) * ASTRIDE + kk + tig;
                afrag[t][0] = __float_as_uint(ab[0]);
                afrag[t][1] = __float_as_uint(ab[8 * ASTRIDE]);
                afrag[t][2] = __float_as_uint(ab[4]);
                afrag[t][3] = __float_as_uint(ab[8 * ASTRIDE + 4]);
            }
#pragma unroll
            for (int j = 0; j < 8; j++) {
                const float* bb = Ws + (kk + tig) * WSTRIDE + wn0 + 8 * j + gid;
                uint32_t b0 = __float_as_uint(bb[0]);
                uint32_t b1 = __float_as_uint(bb[4 * WSTRIDE]);
                mma_tf32(acc[0][j], afrag[0], b0, b1);
                mma_tf32(acc[1][j], afrag[1], b0, b1);
            }
        }
        __syncthreads();
    }

    // epilogue: bias + residual + exact GELU -> bf16 store
#pragma unroll
    for (int t = 0; t < 2; t++) {
#pragma unroll
        for (int half = 0; half < 2; half++) {
            int row = m0 + wm0 + 16 * t + gid + 8 * half;
            if (row >= n) continue;
            const float* hpf = nullptr;
            const __nv_bfloat16* hpb = nullptr;
            if (RES_EMB) {
                hpf = embres + (size_t)__ldg(xres + row) * HH;
            } else {
                hpb = hprev16 + (size_t)row * HH;
            }
            __nv_bfloat16* op = hout16 + (size_t)row * HH;
#pragma unroll
            for (int j = 0; j < 8; j++) {
                int col = wn0 + 8 * j + 2 * tig;
                float2 bv = *(const float2*)(bias + col);
                float2 hr;
                if (RES_EMB) {
                    hr = __ldg((const float2*)(hpf + col));
                } else {
                    __nv_bfloat162 hb = __ldg((const __nv_bfloat162*)(hpb + col));
                    hr = __bfloat1622float2(hb);
                }
                float2 o;
                o.x = gelu_exact(acc[t][j][2 * half]     + bv.x + hr.x);
                o.y = gelu_exact(acc[t][j][2 * half + 1] + bv.y + hr.y);
                __nv_bfloat162 ob = __float22bfloat162_rn(o);
                *(__nv_bfloat162*)(op + col) = ob;
            }
        }
    }
}

// ---------------- pooling: one block per graph, atomic-free (batch is sorted) ----------------
__global__ void pool2_k(const __nv_bfloat16* __restrict__ h16, const int* __restrict__ batch,
                        float* __restrict__ gmean, int n) {
    __shared__ int ss[2];
    __shared__ float red[256];
    int b = blockIdx.x;
    int tid = threadIdx.x;
    if (tid < 2) {
        int target = b + tid;
        int lo = 0, hi = n;
        while (lo < hi) {
            int mid = (lo + hi) >> 1;
            if (__ldg(batch + mid) < target) lo = mid + 1; else hi = mid;
        }
        ss[tid] = lo;
    }
    __syncthreads();
    int start = ss[0], end = ss[1];
    int c = tid & 127;
    int half = tid >> 7;          // 0 or 1: even/odd rows
    float a0 = 0.f, a1 = 0.f, a2 = 0.f, a3 = 0.f;
    int r = start + half;
    for (; r + 6 < end; r += 8) {
        a0 += __bfloat162float(__ldg(h16 + (size_t)r * HH + c));
        a1 += __bfloat162float(__ldg(h16 + (size_t)(r + 2) * HH + c));
        a2 += __bfloat162float(__ldg(h16 + (size_t)(r + 4) * HH + c));
        a3 += __bfloat162float(__ldg(h16 + (size_t)(r + 6) * HH + c));
    }
    for (; r < end; r += 2)
        a0 += __bfloat162float(__ldg(h16 + (size_t)r * HH + c));
    red[tid] = (a0 + a1) + (a2 + a3);
    __syncthreads();
    if (tid < 128) {
        float cntf = fmaxf((float)(end - start), 1.0f);
        gmean[(size_t)b * HH + tid] = (red[tid] + red[tid + 128]) / cntf;
    }
}

// ---------------- final head (gmean already averaged) ----------------
__global__ void final_k(const float* __restrict__ gmean,
                        const float* __restrict__ Wo, const float* __restrict__ bo,
                        const float* __restrict__ gamma, const float* __restrict__ beta,
                        float* __restrict__ out) {
    __shared__ float g[HH];
    __shared__ float rs[8], rq[8];
    int b = blockIdx.x, tid = threadIdx.x;
    if (tid < HH) g[tid] = gmean[(size_t)b * HH + tid];
    __syncthreads();
    float acc = bo[tid];
#pragma unroll 4
    for (int k = 0; k < HH; k++) acc = fmaf(g[k], Wo[k * OUTD + tid], acc);
    float s = acc, q = acc * acc;
#pragma unroll
    for (int o = 16; o; o >>= 1) {
        s += __shfl_xor_sync(0xFFFFFFFFu, s, o);
        q += __shfl_xor_sync(0xFFFFFFFFu, q, o);
    }
    int w = tid >> 5;
    if ((tid & 31) == 0) { rs[w] = s; rq[w] = q; }
    __syncthreads();
    float ts = 0.f, tq = 0.f;
#pragma unroll
    for (int i = 0; i < 8; i++) { ts += rs[i]; tq += rq[i]; }
    float mu  = ts * (1.0f / OUTD);
    float var = tq * (1.0f / OUTD) - mu * mu;
    out[(size_t)b * OUTD + tid] = (acc - mu) * rsqrtf(var + 1e-5f) * gamma[tid] + beta[tid];
}

// ---------------- launch ----------------
extern "C" void kernel_launch(void* const* d_in, const int* in_sizes, int n_in,
                              void* d_out, int out_size) {
    const int* x     = (const int*)d_in[0];
    const int* ei    = (const int*)d_in[1];
    const int* batch = (const int*)d_in[2];
    int off = (n_in >= 13 && in_sizes[3] == 1) ? 4 : 3;
    const float* emb   = (const float*)d_in[off + 0];
    const float* W0    = (const float*)d_in[off + 1];
    const float* b0    = (const float*)d_in[off + 2];
    const float* W1    = (const float*)d_in[off + 3];
    const float* b1    = (const float*)d_in[off + 4];
    const float* Wo    = (const float*)d_in[off + 5];
    const float* bo    = (const float*)d_in[off + 6];
    const float* gamma = (const float*)d_in[off + 7];
    const float* beta  = (const float*)d_in[off + 8];

    int N = in_sizes[0];
    int E = in_sizes[1] / 2;
    int B = out_size / OUTD;

    float *invn, *gsum;
    __nv_bfloat16 *h1, *h2, *agg16;
    int *deg, *cur, *rowptr, *ctr;
    int2 *adjP;
    cudaGetSymbolAddress((void**)&h1,   g_h1);
    cudaGetSymbolAddress((void**)&h2,   g_h2);
    cudaGetSymbolAddress((void**)&agg16, g_agg16);
    cudaGetSymbolAddress((void**)&invn, g_invn);
    cudaGetSymbolAddress((void**)&gsum, g_gsum);
    cudaGetSymbolAddress((void**)&deg,  g_deg);
    cudaGetSymbolAddress((void**)&cur,  g_cur);
    cudaGetSymbolAddress((void**)&rowptr, g_rowptr);
    cudaGetSymbolAddress((void**)&adjP, g_adjP);
    cudaGetSymbolAddress((void**)&ctr,  g_ctr);

    int smem_tc = (128 * ASTRIDE + 64 * WSTRIDE) * 4;   // 69632 bytes
    cudaFuncSetAttribute((const void*)combine_tc_k<1>, cudaFuncAttributeMaxDynamicSharedMemorySize, smem_tc);
    cudaFuncSetAttribute((const void*)combine_tc_k<0>, cudaFuncAttributeMaxDynamicSharedMemorySize, smem_tc);

    const int* src = ei;
    const int* dst = ei + E;

    int cblk = (N + BM - 1) / BM;

    // init + CSR build (no scan: warp-aggregated atomic region assignment)
    init_k<<<256, 256>>>(deg, cur, ctr, N);
    deg_k<<<(E + 255) / 256, 256>>>(src, dst, deg, E);
    assign_k<<<(N + 255) / 256, 256>>>(deg, rowptr, invn, ctr, N);
    fill_k<<<(E + 255) / 256, 256>>>(src, dst, x, rowptr, cur, adjP, E);

    // layer 1: aggregate from hot emb table -> bf16 agg; combine -> bf16 h1
    aggregate1_k<<<(N * 32 + 255) / 256, 256>>>(emb, rowptr, deg, adjP, invn, agg16, N);
    combine_tc_k<1><<<cblk, 256, smem_tc>>>(agg16, nullptr, x, emb, W0, b0, h1, N);

    // layer 2: bf16 gather -> bf16 agg; combine (bf16 residual) -> bf16 h2
    aggregate_k<<<(N * 32 + 255) / 256, 256>>>(h1, rowptr, deg, adjP, invn, agg16, N);
    combine_tc_k<0><<<cblk, 256, smem_tc>>>(agg16, h1, nullptr, nullptr, W1, b1, h2, N);

    // pool (atomic-free, per-graph blocks) + head
    pool2_k<<<B, 256>>>(h2, batch, gsum, N);
    final_k<<<B, 256>>>(gsum, Wo, bo, gamma, beta, (float*)d_out);
}